// round 6
// baseline (speedup 1.0000x reference)
#include <cuda_runtime.h>
#include <cstdint>
#include <math.h>

namespace {

constexpr int SEQ    = 2048;
constexpr int DMODEL = 2048;
constexpr int NHEADS = 16;
constexpr int DHEAD  = 128;
constexpr int MTOT   = 4 * SEQ;          // 8192 rows (B*S)
constexpr int KDIM   = DMODEL;           // 2048
constexpr int NDIM   = NHEADS * DHEAD;   // 2048

constexpr int BM = 128, BN = 128, BK = 16;
constexpr int KTILES = KDIM / BK;        // 128
constexpr int ASTR = BK + 4;             // 20 floats  (conflict-free for A frag reads)
constexpr int BSTR = BN + 8;             // 136 floats (conflict-free for B frag reads)

// Precomputed rotary table: [pos][j] -> (sin, cos), j = pair index 0..31
__device__ float2 g_rope[SEQ * 32];

__global__ void rope_init_kernel() {
    int idx = blockIdx.x * blockDim.x + threadIdx.x;
    if (idx >= SEQ * 32) return;
    int pos = idx >> 5;
    int j   = idx & 31;
    // mimic reference fp32 rounding of the angle, then high-precision sincos
    double freq = pow(10000.0, (double)j / 32.0);
    float ang = (float)pos / (float)freq;
    double s, c;
    sincos((double)ang, &s, &c);
    g_rope[idx] = make_float2((float)s, (float)c);
}

__device__ __forceinline__ uint32_t f2tf32(float f) {
    uint32_t u;
    asm("cvt.rna.tf32.f32 %0, %1;" : "=r"(u) : "f"(f));
    return u;
}

__device__ __forceinline__ void cp16(uint32_t dst, const float* src) {
    asm volatile("cp.async.cg.shared.global [%0], [%1], 16;\n" :: "r"(dst), "l"(src));
}

__device__ __forceinline__ void mma_tf32(float c[4], const uint32_t a[4], const uint32_t b[2]) {
    asm volatile(
        "mma.sync.aligned.m16n8k8.row.col.f32.tf32.tf32.f32 "
        "{%0,%1,%2,%3}, {%4,%5,%6,%7}, {%8,%9}, {%0,%1,%2,%3};\n"
        : "+f"(c[0]), "+f"(c[1]), "+f"(c[2]), "+f"(c[3])
        : "r"(a[0]), "r"(a[1]), "r"(a[2]), "r"(a[3]), "r"(b[0]), "r"(b[1]));
}

__global__ __launch_bounds__(256, 2) void qkv_kernel(
    const float* __restrict__ x,
    const float* __restrict__ Wq, const float* __restrict__ Wk, const float* __restrict__ Wv,
    const float* __restrict__ bq, const float* __restrict__ bk, const float* __restrict__ bv,
    float* __restrict__ out)
{
    __shared__ __align__(16) float As[2][BM][ASTR];
    __shared__ __align__(16) float Bs[2][BK][BSTR];

    const int z    = blockIdx.z;        // 0=Q, 1=K, 2=V
    const int head = blockIdx.x;        // BN == DHEAD: one head per block column
    const int m0   = blockIdx.y * BM;

    const float* W    = (z == 0) ? Wq : (z == 1) ? Wk : Wv;
    const float* bias = (z == 0) ? bq : (z == 1) ? bk : bv;
    const float* Wh   = W + (size_t)head * ((size_t)KDIM * DHEAD);

    const int tid  = threadIdx.x;
    const int lane = tid & 31;
    const int warp = tid >> 5;
    const int wm   = (warp >> 2) * 64;   // 2 warps over M
    const int wn   = (warp & 3) * 32;    // 4 warps over N

    // global->smem load coordinates
    const int arow = tid >> 2;           // 0..63  (two passes of 64 rows)
    const int acol = (tid & 3) * 4;      // 0,4,8,12
    const float* asrc0 = x + (size_t)(m0 + arow) * KDIM + acol;
    const int brow = tid >> 5;           // 0..7   (two passes of 8 k-rows)
    const int bcol = (tid & 31) * 4;     // 0..124
    const float* bsrc0 = Wh + (size_t)brow * DHEAD + bcol;

    float acc[4][4][4];
#pragma unroll
    for (int a = 0; a < 4; ++a)
#pragma unroll
        for (int b = 0; b < 4; ++b)
#pragma unroll
            for (int r = 0; r < 4; ++r) acc[a][b][r] = 0.0f;

    auto load_stage = [&](int stg, int kt) {
        const int k0 = kt * BK;
        cp16((uint32_t)__cvta_generic_to_shared(&As[stg][arow][acol]),      asrc0 + k0);
        cp16((uint32_t)__cvta_generic_to_shared(&As[stg][arow + 64][acol]), asrc0 + k0 + (size_t)64 * KDIM);
        cp16((uint32_t)__cvta_generic_to_shared(&Bs[stg][brow][bcol]),      bsrc0 + (size_t)k0 * DHEAD);
        cp16((uint32_t)__cvta_generic_to_shared(&Bs[stg][brow + 8][bcol]),  bsrc0 + (size_t)(k0 + 8) * DHEAD);
        asm volatile("cp.async.commit_group;\n");
    };

    load_stage(0, 0);

    const int fr = lane >> 2;  // 0..7
    const int fc = lane & 3;   // 0..3

    for (int kt = 0; kt < KTILES; ++kt) {
        asm volatile("cp.async.wait_group 0;\n");
        __syncthreads();
        if (kt + 1 < KTILES) load_stage((kt + 1) & 1, kt + 1);
        const int stg = kt & 1;
#pragma unroll
        for (int ks = 0; ks < 2; ++ks) {
            const int kk = ks * 8;
            uint32_t afr[4][4], bfr[4][2];
#pragma unroll
            for (int mt = 0; mt < 4; ++mt) {
                const int r0 = wm + mt * 16 + fr;
                afr[mt][0] = f2tf32(As[stg][r0][kk + fc]);
                afr[mt][1] = f2tf32(As[stg][r0 + 8][kk + fc]);
                afr[mt][2] = f2tf32(As[stg][r0][kk + fc + 4]);
                afr[mt][3] = f2tf32(As[stg][r0 + 8][kk + fc + 4]);
            }
#pragma unroll
            for (int nt = 0; nt < 4; ++nt) {
                const int c0 = wn + nt * 8 + fr;
                bfr[nt][0] = f2tf32(Bs[stg][kk + fc][c0]);
                bfr[nt][1] = f2tf32(Bs[stg][kk + fc + 4][c0]);
            }
#pragma unroll
            for (int mt = 0; mt < 4; ++mt)
#pragma unroll
                for (int nt = 0; nt < 4; ++nt)
                    mma_tf32(acc[mt][nt], afr[mt], bfr[nt]);
        }
        __syncthreads();
    }

    // ---- epilogue: bias + rotary (Q,K on first 64 head dims) + store ----
    const size_t OUTMAT = (size_t)MTOT * NDIM;
    float* outz = out + OUTMAT * (size_t)(1 + z);
    const int gnb = head * DHEAD;

#pragma unroll
    for (int mt = 0; mt < 4; ++mt) {
        const int gmb = m0 + wm + mt * 16 + fr;
#pragma unroll
        for (int nt = 0; nt < 4; ++nt) {
            const int ln = wn + nt * 8 + 2 * fc;  // head-local column, even
            const int gn = gnb + ln;
            const float2 bb = *reinterpret_cast<const float2*>(bias + gn);
#pragma unroll
            for (int r = 0; r < 2; ++r) {
                const int gm = gmb + r * 8;
                float v0 = acc[mt][nt][2 * r]     + bb.x;
                float v1 = acc[mt][nt][2 * r + 1] + bb.y;
                if (z < 2 && ln < 64) {
                    const int pos = gm & (SEQ - 1);         // row -> sequence position
                    const float2 sc = g_rope[pos * 32 + (ln >> 1)];
                    const float o0 = v0 * sc.y - v1 * sc.x;  // x*cos - x_odd*sin
                    const float o1 = v1 * sc.y + v0 * sc.x;  // x_odd*cos + x*sin
                    v0 = o0; v1 = o1;
                }
                *reinterpret_cast<float2*>(outz + (size_t)gm * NDIM + gn) =
                    make_float2(v0, v1);
            }
        }
    }
}

}  // namespace

extern "C" void kernel_launch(void* const* d_in, const int* in_sizes, int n_in,
                              void* d_out, int out_size) {
    (void)in_sizes; (void)n_in; (void)out_size;
    const float* residual = (const float*)d_in[0];
    const float* x  = (const float*)d_in[1];
    const float* Wq = (const float*)d_in[2];
    const float* Wk = (const float*)d_in[3];
    const float* Wv = (const float*)d_in[4];
    const float* bq = (const float*)d_in[5];
    const float* bk = (const float*)d_in[6];
    const float* bv = (const float*)d_in[7];
    float* out = (float*)d_out;

    // residual passthrough: out[0 : M*N] = residual
    cudaMemcpyAsync(out, residual, (size_t)MTOT * NDIM * sizeof(float),
                    cudaMemcpyDeviceToDevice);

    rope_init_kernel<<<(SEQ * 32 + 255) / 256, 256>>>();

    dim3 grid(NDIM / BN, MTOT / BM, 3);  // (16 heads, 64 row-tiles, q/k/v)
    qkv_kernel<<<grid, 256>>>(x, Wq, Wk, Wv, bq, bk, bv, out);
}

// round 7
// speedup vs baseline: 1.0022x; 1.0022x over previous
#include <cuda_runtime.h>
#include <cstdint>
#include <math.h>

namespace {

constexpr int SEQ    = 2048;
constexpr int DMODEL = 2048;
constexpr int NHEADS = 16;
constexpr int DHEAD  = 128;
constexpr int MTOT   = 4 * SEQ;          // 8192 rows (B*S)
constexpr int KDIM   = DMODEL;           // 2048
constexpr int NDIM   = NHEADS * DHEAD;   // 2048

constexpr int BM = 128, BN = 128, BK = 16;
constexpr int KTILES = KDIM / BK;        // 128
constexpr int ASTR = BK + 4;             // 20 floats  (conflict-free for A frag reads)
constexpr int BSTR = BN + 8;             // 136 floats (conflict-free for B frag reads)

// Precomputed rotary table: [pos][j] -> (sin, cos), j = pair index 0..31
__device__ float2 g_rope[SEQ * 32];

__global__ void rope_init_kernel() {
    int idx = blockIdx.x * blockDim.x + threadIdx.x;
    if (idx >= SEQ * 32) return;
    int pos = idx >> 5;
    int j   = idx & 31;
    // mimic reference fp32 rounding of the angle, then high-precision sincos
    double freq = pow(10000.0, (double)j / 32.0);
    float ang = (float)pos / (float)freq;
    double s, c;
    sincos((double)ang, &s, &c);
    g_rope[idx] = make_float2((float)s, (float)c);
}

__device__ __forceinline__ uint32_t f2tf32(float f) {
    uint32_t u;
    asm("cvt.rna.tf32.f32 %0, %1;" : "=r"(u) : "f"(f));
    return u;
}

__device__ __forceinline__ void cp16(uint32_t dst, const float* src) {
    asm volatile("cp.async.cg.shared.global [%0], [%1], 16;\n" :: "r"(dst), "l"(src));
}

__device__ __forceinline__ void mma_tf32(float c[4], const uint32_t a[4], const uint32_t b[2]) {
    asm volatile(
        "mma.sync.aligned.m16n8k8.row.col.f32.tf32.tf32.f32 "
        "{%0,%1,%2,%3}, {%4,%5,%6,%7}, {%8,%9}, {%0,%1,%2,%3};\n"
        : "+f"(c[0]), "+f"(c[1]), "+f"(c[2]), "+f"(c[3])
        : "r"(a[0]), "r"(a[1]), "r"(a[2]), "r"(a[3]), "r"(b[0]), "r"(b[1]));
}

__global__ __launch_bounds__(256, 2) void qkv_kernel(
    const float* __restrict__ x,
    const float* __restrict__ Wq, const float* __restrict__ Wk, const float* __restrict__ Wv,
    const float* __restrict__ bq, const float* __restrict__ bk, const float* __restrict__ bv,
    float* __restrict__ out)
{
    __shared__ __align__(16) float As[2][BM][ASTR];
    __shared__ __align__(16) float Bs[2][BK][BSTR];

    const int z    = blockIdx.z;        // 0=Q, 1=K, 2=V
    const int head = blockIdx.x;        // BN == DHEAD: one head per block column
    const int m0   = blockIdx.y * BM;

    const float* W    = (z == 0) ? Wq : (z == 1) ? Wk : Wv;
    const float* bias = (z == 0) ? bq : (z == 1) ? bk : bv;
    const float* Wh   = W + (size_t)head * ((size_t)KDIM * DHEAD);

    const int tid  = threadIdx.x;
    const int lane = tid & 31;
    const int warp = tid >> 5;
    const int wm   = (warp >> 2) * 64;   // 2 warps over M
    const int wn   = (warp & 3) * 32;    // 4 warps over N

    // global->smem load coordinates
    const int arow = tid >> 2;           // 0..63  (two passes of 64 rows)
    const int acol = (tid & 3) * 4;      // 0,4,8,12
    const float* asrc0 = x + (size_t)(m0 + arow) * KDIM + acol;
    const int brow = tid >> 5;           // 0..7   (two passes of 8 k-rows)
    const int bcol = (tid & 31) * 4;     // 0..124
    const float* bsrc0 = Wh + (size_t)brow * DHEAD + bcol;

    float acc[4][4][4];
#pragma unroll
    for (int a = 0; a < 4; ++a)
#pragma unroll
        for (int b = 0; b < 4; ++b)
#pragma unroll
            for (int r = 0; r < 4; ++r) acc[a][b][r] = 0.0f;

    auto load_stage = [&](int stg, int kt) {
        const int k0 = kt * BK;
        cp16((uint32_t)__cvta_generic_to_shared(&As[stg][arow][acol]),      asrc0 + k0);
        cp16((uint32_t)__cvta_generic_to_shared(&As[stg][arow + 64][acol]), asrc0 + k0 + (size_t)64 * KDIM);
        cp16((uint32_t)__cvta_generic_to_shared(&Bs[stg][brow][bcol]),      bsrc0 + (size_t)k0 * DHEAD);
        cp16((uint32_t)__cvta_generic_to_shared(&Bs[stg][brow + 8][bcol]),  bsrc0 + (size_t)(k0 + 8) * DHEAD);
        asm volatile("cp.async.commit_group;\n");
    };

    load_stage(0, 0);

    const int fr = lane >> 2;  // 0..7
    const int fc = lane & 3;   // 0..3

    for (int kt = 0; kt < KTILES; ++kt) {
        asm volatile("cp.async.wait_group 0;\n");
        __syncthreads();
        if (kt + 1 < KTILES) load_stage((kt + 1) & 1, kt + 1);
        const int stg = kt & 1;
#pragma unroll
        for (int ks = 0; ks < 2; ++ks) {
            const int kk = ks * 8;
            uint32_t afr[4][4], bfr[4][2];
#pragma unroll
            for (int mt = 0; mt < 4; ++mt) {
                const int r0 = wm + mt * 16 + fr;
                afr[mt][0] = f2tf32(As[stg][r0][kk + fc]);
                afr[mt][1] = f2tf32(As[stg][r0 + 8][kk + fc]);
                afr[mt][2] = f2tf32(As[stg][r0][kk + fc + 4]);
                afr[mt][3] = f2tf32(As[stg][r0 + 8][kk + fc + 4]);
            }
#pragma unroll
            for (int nt = 0; nt < 4; ++nt) {
                const int c0 = wn + nt * 8 + fr;
                bfr[nt][0] = f2tf32(Bs[stg][kk + fc][c0]);
                bfr[nt][1] = f2tf32(Bs[stg][kk + fc + 4][c0]);
            }
#pragma unroll
            for (int mt = 0; mt < 4; ++mt)
#pragma unroll
                for (int nt = 0; nt < 4; ++nt)
                    mma_tf32(acc[mt][nt], afr[mt], bfr[nt]);
        }
        __syncthreads();
    }

    // ---- epilogue: bias + rotary (Q,K on first 64 head dims) + store ----
    const size_t OUTMAT = (size_t)MTOT * NDIM;
    float* outz = out + OUTMAT * (size_t)(1 + z);
    const int gnb = head * DHEAD;

#pragma unroll
    for (int mt = 0; mt < 4; ++mt) {
        const int gmb = m0 + wm + mt * 16 + fr;
#pragma unroll
        for (int nt = 0; nt < 4; ++nt) {
            const int ln = wn + nt * 8 + 2 * fc;  // head-local column, even
            const int gn = gnb + ln;
            const float2 bb = *reinterpret_cast<const float2*>(bias + gn);
#pragma unroll
            for (int r = 0; r < 2; ++r) {
                const int gm = gmb + r * 8;
                float v0 = acc[mt][nt][2 * r]     + bb.x;
                float v1 = acc[mt][nt][2 * r + 1] + bb.y;
                if (z < 2 && ln < 64) {
                    const int pos = gm & (SEQ - 1);         // row -> sequence position
                    const float2 sc = g_rope[pos * 32 + (ln >> 1)];
                    const float o0 = v0 * sc.y - v1 * sc.x;  // x*cos - x_odd*sin
                    const float o1 = v1 * sc.y + v0 * sc.x;  // x_odd*cos + x*sin
                    v0 = o0; v1 = o1;
                }
                *reinterpret_cast<float2*>(outz + (size_t)gm * NDIM + gn) =
                    make_float2(v0, v1);
            }
        }
    }
}

}  // namespace

extern "C" void kernel_launch(void* const* d_in, const int* in_sizes, int n_in,
                              void* d_out, int out_size) {
    (void)in_sizes; (void)n_in; (void)out_size;
    const float* residual = (const float*)d_in[0];
    const float* x  = (const float*)d_in[1];
    const float* Wq = (const float*)d_in[2];
    const float* Wk = (const float*)d_in[3];
    const float* Wv = (const float*)d_in[4];
    const float* bq = (const float*)d_in[5];
    const float* bk = (const float*)d_in[6];
    const float* bv = (const float*)d_in[7];
    float* out = (float*)d_out;

    // residual passthrough: out[0 : M*N] = residual
    cudaMemcpyAsync(out, residual, (size_t)MTOT * NDIM * sizeof(float),
                    cudaMemcpyDeviceToDevice);

    rope_init_kernel<<<(SEQ * 32 + 255) / 256, 256>>>();

    dim3 grid(NDIM / BN, MTOT / BM, 3);  // (16 heads, 64 row-tiles, q/k/v)
    qkv_kernel<<<grid, 256>>>(x, Wq, Wk, Wv, bq, bk, bv, out);
}

// round 8
// speedup vs baseline: 1.0024x; 1.0002x over previous
#include <cuda_runtime.h>
#include <cstdint>
#include <math.h>

namespace {

constexpr int SEQ    = 2048;
constexpr int DMODEL = 2048;
constexpr int NHEADS = 16;
constexpr int DHEAD  = 128;
constexpr int MTOT   = 4 * SEQ;          // 8192 rows (B*S)
constexpr int KDIM   = DMODEL;           // 2048
constexpr int NDIM   = NHEADS * DHEAD;   // 2048

constexpr int BM = 128, BN = 128, BK = 16;
constexpr int KTILES = KDIM / BK;        // 128
constexpr int ASTR = BK + 4;             // 20 floats  (conflict-free for A frag reads)
constexpr int BSTR = BN + 8;             // 136 floats (conflict-free for B frag reads)

// Precomputed rotary table: [pos][j] -> (sin, cos), j = pair index 0..31
__device__ float2 g_rope[SEQ * 32];

__global__ void rope_init_kernel() {
    int idx = blockIdx.x * blockDim.x + threadIdx.x;
    if (idx >= SEQ * 32) return;
    int pos = idx >> 5;
    int j   = idx & 31;
    // mimic reference fp32 rounding of the angle, then high-precision sincos
    double freq = pow(10000.0, (double)j / 32.0);
    float ang = (float)pos / (float)freq;
    double s, c;
    sincos((double)ang, &s, &c);
    g_rope[idx] = make_float2((float)s, (float)c);
}

__device__ __forceinline__ uint32_t f2tf32(float f) {
    uint32_t u;
    asm("cvt.rna.tf32.f32 %0, %1;" : "=r"(u) : "f"(f));
    return u;
}

__device__ __forceinline__ void cp16(uint32_t dst, const float* src) {
    asm volatile("cp.async.cg.shared.global [%0], [%1], 16;\n" :: "r"(dst), "l"(src));
}

__device__ __forceinline__ void mma_tf32(float c[4], const uint32_t a[4], const uint32_t b[2]) {
    asm volatile(
        "mma.sync.aligned.m16n8k8.row.col.f32.tf32.tf32.f32 "
        "{%0,%1,%2,%3}, {%4,%5,%6,%7}, {%8,%9}, {%0,%1,%2,%3};\n"
        : "+f"(c[0]), "+f"(c[1]), "+f"(c[2]), "+f"(c[3])
        : "r"(a[0]), "r"(a[1]), "r"(a[2]), "r"(a[3]), "r"(b[0]), "r"(b[1]));
}

__global__ __launch_bounds__(256, 2) void qkv_kernel(
    const float* __restrict__ x,
    const float* __restrict__ Wq, const float* __restrict__ Wk, const float* __restrict__ Wv,
    const float* __restrict__ bq, const float* __restrict__ bk, const float* __restrict__ bv,
    float* __restrict__ out)
{
    __shared__ __align__(16) float As[2][BM][ASTR];
    __shared__ __align__(16) float Bs[2][BK][BSTR];

    const int z    = blockIdx.z;        // 0=Q, 1=K, 2=V
    const int head = blockIdx.x;        // BN == DHEAD: one head per block column
    const int m0   = blockIdx.y * BM;

    const float* W    = (z == 0) ? Wq : (z == 1) ? Wk : Wv;
    const float* bias = (z == 0) ? bq : (z == 1) ? bk : bv;
    const float* Wh   = W + (size_t)head * ((size_t)KDIM * DHEAD);

    const int tid  = threadIdx.x;
    const int lane = tid & 31;
    const int warp = tid >> 5;
    const int wm   = (warp >> 2) * 64;   // 2 warps over M
    const int wn   = (warp & 3) * 32;    // 4 warps over N

    // global->smem load coordinates
    const int arow = tid >> 2;           // 0..63  (two passes of 64 rows)
    const int acol = (tid & 3) * 4;      // 0,4,8,12
    const float* asrc0 = x + (size_t)(m0 + arow) * KDIM + acol;
    const int brow = tid >> 5;           // 0..7   (two passes of 8 k-rows)
    const int bcol = (tid & 31) * 4;     // 0..124
    const float* bsrc0 = Wh + (size_t)brow * DHEAD + bcol;

    float acc[4][4][4];
#pragma unroll
    for (int a = 0; a < 4; ++a)
#pragma unroll
        for (int b = 0; b < 4; ++b)
#pragma unroll
            for (int r = 0; r < 4; ++r) acc[a][b][r] = 0.0f;

    auto load_stage = [&](int stg, int kt) {
        const int k0 = kt * BK;
        cp16((uint32_t)__cvta_generic_to_shared(&As[stg][arow][acol]),      asrc0 + k0);
        cp16((uint32_t)__cvta_generic_to_shared(&As[stg][arow + 64][acol]), asrc0 + k0 + (size_t)64 * KDIM);
        cp16((uint32_t)__cvta_generic_to_shared(&Bs[stg][brow][bcol]),      bsrc0 + (size_t)k0 * DHEAD);
        cp16((uint32_t)__cvta_generic_to_shared(&Bs[stg][brow + 8][bcol]),  bsrc0 + (size_t)(k0 + 8) * DHEAD);
        asm volatile("cp.async.commit_group;\n");
    };

    load_stage(0, 0);

    const int fr = lane >> 2;  // 0..7
    const int fc = lane & 3;   // 0..3

    for (int kt = 0; kt < KTILES; ++kt) {
        asm volatile("cp.async.wait_group 0;\n");
        __syncthreads();
        if (kt + 1 < KTILES) load_stage((kt + 1) & 1, kt + 1);
        const int stg = kt & 1;
#pragma unroll
        for (int ks = 0; ks < 2; ++ks) {
            const int kk = ks * 8;
            uint32_t afr[4][4], bfr[4][2];
#pragma unroll
            for (int mt = 0; mt < 4; ++mt) {
                const int r0 = wm + mt * 16 + fr;
                afr[mt][0] = f2tf32(As[stg][r0][kk + fc]);
                afr[mt][1] = f2tf32(As[stg][r0 + 8][kk + fc]);
                afr[mt][2] = f2tf32(As[stg][r0][kk + fc + 4]);
                afr[mt][3] = f2tf32(As[stg][r0 + 8][kk + fc + 4]);
            }
#pragma unroll
            for (int nt = 0; nt < 4; ++nt) {
                const int c0 = wn + nt * 8 + fr;
                bfr[nt][0] = f2tf32(Bs[stg][kk + fc][c0]);
                bfr[nt][1] = f2tf32(Bs[stg][kk + fc + 4][c0]);
            }
#pragma unroll
            for (int mt = 0; mt < 4; ++mt)
#pragma unroll
                for (int nt = 0; nt < 4; ++nt)
                    mma_tf32(acc[mt][nt], afr[mt], bfr[nt]);
        }
        __syncthreads();
    }

    // ---- epilogue: bias + rotary (Q,K on first 64 head dims) + store ----
    const size_t OUTMAT = (size_t)MTOT * NDIM;
    float* outz = out + OUTMAT * (size_t)(1 + z);
    const int gnb = head * DHEAD;

#pragma unroll
    for (int mt = 0; mt < 4; ++mt) {
        const int gmb = m0 + wm + mt * 16 + fr;
#pragma unroll
        for (int nt = 0; nt < 4; ++nt) {
            const int ln = wn + nt * 8 + 2 * fc;  // head-local column, even
            const int gn = gnb + ln;
            const float2 bb = *reinterpret_cast<const float2*>(bias + gn);
#pragma unroll
            for (int r = 0; r < 2; ++r) {
                const int gm = gmb + r * 8;
                float v0 = acc[mt][nt][2 * r]     + bb.x;
                float v1 = acc[mt][nt][2 * r + 1] + bb.y;
                if (z < 2 && ln < 64) {
                    const int pos = gm & (SEQ - 1);         // row -> sequence position
                    const float2 sc = g_rope[pos * 32 + (ln >> 1)];
                    const float o0 = v0 * sc.y - v1 * sc.x;  // x*cos - x_odd*sin
                    const float o1 = v1 * sc.y + v0 * sc.x;  // x_odd*cos + x*sin
                    v0 = o0; v1 = o1;
                }
                *reinterpret_cast<float2*>(outz + (size_t)gm * NDIM + gn) =
                    make_float2(v0, v1);
            }
        }
    }
}

}  // namespace

extern "C" void kernel_launch(void* const* d_in, const int* in_sizes, int n_in,
                              void* d_out, int out_size) {
    (void)in_sizes; (void)n_in; (void)out_size;
    const float* residual = (const float*)d_in[0];
    const float* x  = (const float*)d_in[1];
    const float* Wq = (const float*)d_in[2];
    const float* Wk = (const float*)d_in[3];
    const float* Wv = (const float*)d_in[4];
    const float* bq = (const float*)d_in[5];
    const float* bk = (const float*)d_in[6];
    const float* bv = (const float*)d_in[7];
    float* out = (float*)d_out;

    // residual passthrough: out[0 : M*N] = residual
    cudaMemcpyAsync(out, residual, (size_t)MTOT * NDIM * sizeof(float),
                    cudaMemcpyDeviceToDevice);

    rope_init_kernel<<<(SEQ * 32 + 255) / 256, 256>>>();

    dim3 grid(NDIM / BN, MTOT / BM, 3);  // (16 heads, 64 row-tiles, q/k/v)
    qkv_kernel<<<grid, 256>>>(x, Wq, Wk, Wv, bq, bk, bv, out);
}

// round 9
// speedup vs baseline: 1.0027x; 1.0002x over previous
#include <cuda_runtime.h>
#include <cstdint>
#include <math.h>

namespace {

constexpr int SEQ    = 2048;
constexpr int DMODEL = 2048;
constexpr int NHEADS = 16;
constexpr int DHEAD  = 128;
constexpr int MTOT   = 4 * SEQ;          // 8192 rows (B*S)
constexpr int KDIM   = DMODEL;           // 2048
constexpr int NDIM   = NHEADS * DHEAD;   // 2048

constexpr int BM = 128, BN = 128, BK = 16;
constexpr int KTILES = KDIM / BK;        // 128
constexpr int ASTR = BK + 4;             // 20 floats  (conflict-free for A frag reads)
constexpr int BSTR = BN + 8;             // 136 floats (conflict-free for B frag reads)

// Precomputed rotary table: [pos][j] -> (sin, cos), j = pair index 0..31
__device__ float2 g_rope[SEQ * 32];

__global__ void rope_init_kernel() {
    int idx = blockIdx.x * blockDim.x + threadIdx.x;
    if (idx >= SEQ * 32) return;
    int pos = idx >> 5;
    int j   = idx & 31;
    // mimic reference fp32 rounding of the angle, then high-precision sincos
    double freq = pow(10000.0, (double)j / 32.0);
    float ang = (float)pos / (float)freq;
    double s, c;
    sincos((double)ang, &s, &c);
    g_rope[idx] = make_float2((float)s, (float)c);
}

__device__ __forceinline__ uint32_t f2tf32(float f) {
    uint32_t u;
    asm("cvt.rna.tf32.f32 %0, %1;" : "=r"(u) : "f"(f));
    return u;
}

__device__ __forceinline__ void cp16(uint32_t dst, const float* src) {
    asm volatile("cp.async.cg.shared.global [%0], [%1], 16;\n" :: "r"(dst), "l"(src));
}

__device__ __forceinline__ void mma_tf32(float c[4], const uint32_t a[4], const uint32_t b[2]) {
    asm volatile(
        "mma.sync.aligned.m16n8k8.row.col.f32.tf32.tf32.f32 "
        "{%0,%1,%2,%3}, {%4,%5,%6,%7}, {%8,%9}, {%0,%1,%2,%3};\n"
        : "+f"(c[0]), "+f"(c[1]), "+f"(c[2]), "+f"(c[3])
        : "r"(a[0]), "r"(a[1]), "r"(a[2]), "r"(a[3]), "r"(b[0]), "r"(b[1]));
}

__global__ __launch_bounds__(256, 2) void qkv_kernel(
    const float* __restrict__ x,
    const float* __restrict__ Wq, const float* __restrict__ Wk, const float* __restrict__ Wv,
    const float* __restrict__ bq, const float* __restrict__ bk, const float* __restrict__ bv,
    float* __restrict__ out)
{
    __shared__ __align__(16) float As[2][BM][ASTR];
    __shared__ __align__(16) float Bs[2][BK][BSTR];

    const int z    = blockIdx.z;        // 0=Q, 1=K, 2=V
    const int head = blockIdx.x;        // BN == DHEAD: one head per block column
    const int m0   = blockIdx.y * BM;

    const float* W    = (z == 0) ? Wq : (z == 1) ? Wk : Wv;
    const float* bias = (z == 0) ? bq : (z == 1) ? bk : bv;
    const float* Wh   = W + (size_t)head * ((size_t)KDIM * DHEAD);

    const int tid  = threadIdx.x;
    const int lane = tid & 31;
    const int warp = tid >> 5;
    const int wm   = (warp >> 2) * 64;   // 2 warps over M
    const int wn   = (warp & 3) * 32;    // 4 warps over N

    // global->smem load coordinates
    const int arow = tid >> 2;           // 0..63  (two passes of 64 rows)
    const int acol = (tid & 3) * 4;      // 0,4,8,12
    const float* asrc0 = x + (size_t)(m0 + arow) * KDIM + acol;
    const int brow = tid >> 5;           // 0..7   (two passes of 8 k-rows)
    const int bcol = (tid & 31) * 4;     // 0..124
    const float* bsrc0 = Wh + (size_t)brow * DHEAD + bcol;

    float acc[4][4][4];
#pragma unroll
    for (int a = 0; a < 4; ++a)
#pragma unroll
        for (int b = 0; b < 4; ++b)
#pragma unroll
            for (int r = 0; r < 4; ++r) acc[a][b][r] = 0.0f;

    auto load_stage = [&](int stg, int kt) {
        const int k0 = kt * BK;
        cp16((uint32_t)__cvta_generic_to_shared(&As[stg][arow][acol]),      asrc0 + k0);
        cp16((uint32_t)__cvta_generic_to_shared(&As[stg][arow + 64][acol]), asrc0 + k0 + (size_t)64 * KDIM);
        cp16((uint32_t)__cvta_generic_to_shared(&Bs[stg][brow][bcol]),      bsrc0 + (size_t)k0 * DHEAD);
        cp16((uint32_t)__cvta_generic_to_shared(&Bs[stg][brow + 8][bcol]),  bsrc0 + (size_t)(k0 + 8) * DHEAD);
        asm volatile("cp.async.commit_group;\n");
    };

    load_stage(0, 0);

    const int fr = lane >> 2;  // 0..7
    const int fc = lane & 3;   // 0..3

    for (int kt = 0; kt < KTILES; ++kt) {
        asm volatile("cp.async.wait_group 0;\n");
        __syncthreads();
        if (kt + 1 < KTILES) load_stage((kt + 1) & 1, kt + 1);
        const int stg = kt & 1;
#pragma unroll
        for (int ks = 0; ks < 2; ++ks) {
            const int kk = ks * 8;
            uint32_t afr[4][4], bfr[4][2];
#pragma unroll
            for (int mt = 0; mt < 4; ++mt) {
                const int r0 = wm + mt * 16 + fr;
                afr[mt][0] = f2tf32(As[stg][r0][kk + fc]);
                afr[mt][1] = f2tf32(As[stg][r0 + 8][kk + fc]);
                afr[mt][2] = f2tf32(As[stg][r0][kk + fc + 4]);
                afr[mt][3] = f2tf32(As[stg][r0 + 8][kk + fc + 4]);
            }
#pragma unroll
            for (int nt = 0; nt < 4; ++nt) {
                const int c0 = wn + nt * 8 + fr;
                bfr[nt][0] = f2tf32(Bs[stg][kk + fc][c0]);
                bfr[nt][1] = f2tf32(Bs[stg][kk + fc + 4][c0]);
            }
#pragma unroll
            for (int mt = 0; mt < 4; ++mt)
#pragma unroll
                for (int nt = 0; nt < 4; ++nt)
                    mma_tf32(acc[mt][nt], afr[mt], bfr[nt]);
        }
        __syncthreads();
    }

    // ---- epilogue: bias + rotary (Q,K on first 64 head dims) + store ----
    const size_t OUTMAT = (size_t)MTOT * NDIM;
    float* outz = out + OUTMAT * (size_t)(1 + z);
    const int gnb = head * DHEAD;

#pragma unroll
    for (int mt = 0; mt < 4; ++mt) {
        const int gmb = m0 + wm + mt * 16 + fr;
#pragma unroll
        for (int nt = 0; nt < 4; ++nt) {
            const int ln = wn + nt * 8 + 2 * fc;  // head-local column, even
            const int gn = gnb + ln;
            const float2 bb = *reinterpret_cast<const float2*>(bias + gn);
#pragma unroll
            for (int r = 0; r < 2; ++r) {
                const int gm = gmb + r * 8;
                float v0 = acc[mt][nt][2 * r]     + bb.x;
                float v1 = acc[mt][nt][2 * r + 1] + bb.y;
                if (z < 2 && ln < 64) {
                    const int pos = gm & (SEQ - 1);         // row -> sequence position
                    const float2 sc = g_rope[pos * 32 + (ln >> 1)];
                    const float o0 = v0 * sc.y - v1 * sc.x;  // x*cos - x_odd*sin
                    const float o1 = v1 * sc.y + v0 * sc.x;  // x_odd*cos + x*sin
                    v0 = o0; v1 = o1;
                }
                *reinterpret_cast<float2*>(outz + (size_t)gm * NDIM + gn) =
                    make_float2(v0, v1);
            }
        }
    }
}

}  // namespace

extern "C" void kernel_launch(void* const* d_in, const int* in_sizes, int n_in,
                              void* d_out, int out_size) {
    (void)in_sizes; (void)n_in; (void)out_size;
    const float* residual = (const float*)d_in[0];
    const float* x  = (const float*)d_in[1];
    const float* Wq = (const float*)d_in[2];
    const float* Wk = (const float*)d_in[3];
    const float* Wv = (const float*)d_in[4];
    const float* bq = (const float*)d_in[5];
    const float* bk = (const float*)d_in[6];
    const float* bv = (const float*)d_in[7];
    float* out = (float*)d_out;

    // residual passthrough: out[0 : M*N] = residual
    cudaMemcpyAsync(out, residual, (size_t)MTOT * NDIM * sizeof(float),
                    cudaMemcpyDeviceToDevice);

    rope_init_kernel<<<(SEQ * 32 + 255) / 256, 256>>>();

    dim3 grid(NDIM / BN, MTOT / BM, 3);  // (16 heads, 64 row-tiles, q/k/v)
    qkv_kernel<<<grid, 256>>>(x, Wq, Wk, Wv, bq, bk, bv, out);
}